// round 11
// baseline (speedup 1.0000x reference)
#include <cuda_runtime.h>

namespace {

constexpr int RAD   = 7;          // N = 2*ceil(2.5)+1 = 7
constexpr int TBX   = 32;         // threads x
constexpr int TBY   = 4;          // threads y
constexpr int PXY   = 4;          // pixels per thread in y
constexpr int TILEY = TBY * PXY;  // 16 output rows per block
constexpr int SW    = TBX + 2*RAD;    // 46
constexpr int SH    = TILEY + 2*RAD;  // 30
constexpr int IMH   = 1080;
constexpr int IMW   = 1920;
constexpr int CH    = 11;

#define EPSF  1e-4f
#define FCAP  14426.950408889634f          /* 1e4 * log2e */
#define NC2   -0.72134752044448f           /* -0.5*log2e  */

// NINVD_L2E[k] = -log2(e)/sqrt(k); k=0 sentinel -1e30: invdz*(-1e30) -> -huge
// -> fmax(., -FCAP) = -FCAP, matching reference den = max(dz*0, eps) = eps
// (zd = 0 at dsi = 0 anyway).
__device__ constexpr float NINVD_L2E[99] = {
    -1e30f,       -1.44269504f, -1.02014424f, -0.83293944f, -0.72134752f,
    -0.64519935f, -0.58898486f, -0.54529656f, -0.51007212f, -0.48089835f,
    -0.45621984f, -0.43498237f, -0.41646972f, -0.40012747f, -0.38556183f,
    -0.37247373f, -0.36067376f, -0.34990480f, -0.34009409f, -0.33102480f,
    -0.32259967f, -0.31482513f, -0.30758643f, -0.30082509f, -0.29449243f,
    -0.28853901f, -0.28293539f, -0.27764648f, -0.27264828f, -0.26790684f,
    -0.26340594f, -0.25912240f, -0.25503606f, -0.25114328f, -0.24742265f,
    -0.24386200f, -0.24044918f, -0.23717857f, -0.23403768f, -0.23101807f,
    -0.22810992f, -0.22531137f, -0.22261272f, -0.22000923f, -0.21749119f,
    -0.21506125f, -0.21271045f, -0.21043517f, -0.20823486f, -0.20609929f,
    -0.20403378f, -0.20202950f, -0.20008659f, -0.19819969f, -0.19636738f,
    -0.19458680f, -0.19284900f, -0.19115746f, -0.18950668f, -0.18789521f,
    -0.18633688f, -0.18480333f, -0.18331146f, -0.18184540f, -0.18041844f,
    -0.17902041f, -0.17766033f, -0.17632993f, -0.17501816f, -0.17374384f,
    -0.17248900f, -0.17126993f, -0.17004704f, -0.16888040f, -0.16773528f,
    -0.16659174f, -0.16549221f, -0.16440389f, -0.16334410f, -0.16231653f,
    -0.16129984f, -0.16029945f, -0.15932285f, -0.15835942f, -0.15741374f,
    -0.15648424f, -0.15557203f, -0.15467385f, -0.15379850f, -0.15293093f,
    -0.15207893f, -0.15123993f, -0.15041596f, -0.14960526f, -0.14880778f,
    -0.14801817f, -0.14724766f, -0.14648368f, -0.14574043f
};

__device__ __forceinline__ float ex2f_(float x) {
    float y; asm("ex2.approx.f32 %0, %1;" : "=f"(y) : "f"(x)); return y;
}
__device__ __forceinline__ float lg2f_(float x) {
    float y; asm("lg2.approx.f32 %0, %1;" : "=f"(y) : "f"(x)); return y;
}
__device__ __forceinline__ float rcpf_(float x) {
    float y; asm("rcp.approx.f32 %0, %1;" : "=f"(y) : "f"(x)); return y;
}

// ---- packed f32x2 helpers (sm_103a) ----
typedef unsigned long long u64;
__device__ __forceinline__ u64 pack2_(float lo, float hi) {
    u64 d; asm("mov.b64 %0, {%1, %2};" : "=l"(d) : "f"(lo), "f"(hi)); return d;
}
__device__ __forceinline__ void unpack2_(float& lo, float& hi, u64 v) {
    asm("mov.b64 {%0, %1}, %2;" : "=f"(lo), "=f"(hi) : "l"(v));
}
__device__ __forceinline__ u64 mul2_(u64 a, u64 b) {
    u64 d; asm("mul.rn.f32x2 %0, %1, %2;" : "=l"(d) : "l"(a), "l"(b)); return d;
}
__device__ __forceinline__ u64 fma2_(u64 a, u64 b, u64 c) {
    u64 d; asm("fma.rn.f32x2 %0, %1, %2, %3;" : "=l"(d) : "l"(a), "l"(b), "l"(c));
    return d;
}
__device__ __forceinline__ u64 add2_(u64 a, u64 b) {
    u64 d; asm("add.rn.f32x2 %0, %1, %2;" : "=l"(d) : "l"(a), "l"(b)); return d;
}

// Per-pixel scalar weight. act/dsi are compile-time after full unroll.
// w = ex2( 128*lg2(sat(dot)) + |zd| * max(invdz*(-c), -FCAP) + NC2*dsi )
// sat(dot)<=0 -> lg2 = -inf -> w = 0 (matches reference eps^128 underflow).
__device__ __forceinline__ float wpix_(bool act, float dotv, float ztap,
                                       float Zc, float invdz, int dsi)
{
    if (!act) return 0.0f;
    float lt  = lg2f_(__saturatef(dotv));
    float nfp = fmaxf(invdz * NINVD_L2E[dsi], -FCAP);   // <= 0
    float zd  = ztap - Zc;
    return ex2f_(fmaf(lt, 128.0f, fmaf(fabsf(zd), nfp, NC2 * (float)dsi)));
}

} // namespace

__global__ void __launch_bounds__(TBX*TBY, 5)
BilateralDenoiser_44427141710593_kernel(const float* __restrict__ in,
                                        float* __restrict__ out)
{
    __shared__ float4 s_nz[SH * SW];   // (nrm.x, nrm.y, nrm.z, z)
    __shared__ float4 s_cd[SH * SW];   // (col.r, col.g, col.b, dz)

    const int bx  = blockIdx.x * TBX;
    const int by  = blockIdx.y * TILEY;
    const int tid = threadIdx.y * TBX + threadIdx.x;

    // Cooperative halo load; OOB -> zeros => dot=0 -> w=0 (matches reference).
    #pragma unroll
    for (int i = tid; i < SH * SW; i += TBX * TBY) {
        const int ly = i / SW;
        const int lx = i - ly * SW;
        const int gy = by + ly - RAD;
        const int gx = bx + lx - RAD;
        float4 nz = make_float4(0.f, 0.f, 0.f, 0.f);
        float4 cd = make_float4(0.f, 0.f, 0.f, 0.f);
        if ((unsigned)gy < (unsigned)IMH && (unsigned)gx < (unsigned)IMW) {
            const float* p = in + ((size_t)gy * IMW + gx) * CH;
            cd.x = p[0]; cd.y = p[1]; cd.z = p[2];      // col
            nz.x = p[3]; nz.y = p[4]; nz.z = p[5];      // nrm
            nz.w = p[9];                                 // z
            cd.w = p[10];                                // dz
        }
        s_nz[i] = nz;
        s_cd[i] = cd;
    }
    __syncthreads();

    const int c0 = (threadIdx.y * PXY + RAD) * SW + (threadIdx.x + RAD);
    const float4* __restrict__ snz = s_nz + c0;
    const float4* __restrict__ scd = s_cd + c0;

    // Per-pixel center constants.
    float Zc[PXY], ivd[PXY], nxx[PXY], nyy[PXY], nzz[PXY];
    #pragma unroll
    for (int p = 0; p < PXY; ++p) {
        const float4 n = snz[p * SW];
        nxx[p] = n.x; nyy[p] = n.y; nzz[p] = n.z; Zc[p] = n.w;
        ivd[p] = rcpf_(fmaxf(scd[p * SW].w, 0.0f));
    }
    const u64 NXa = pack2_(nxx[0], nxx[1]), NYa = pack2_(nyy[0], nyy[1]),
              NZa = pack2_(nzz[0], nzz[1]);
    const u64 NXb = pack2_(nxx[2], nxx[3]), NYb = pack2_(nyy[2], nyy[3]),
              NZb = pack2_(nzz[2], nzz[3]);

    // Packed accumulators: pair A = pixels (0,1), pair B = pixels (2,3).
    u64 arA = 0ull, agA = 0ull, abA = 0ull, awA = 0ull;
    u64 arB = 0ull, agB = 0ull, abB = 0ull, awB = 0ull;

    #pragma unroll
    for (int dy = -RAD; dy <= RAD + PXY - 1; ++dy) {
        #pragma unroll
        for (int dx = -RAD; dx <= RAD; ++dx) {
            const float4 nz = snz[dy*SW + dx];
            const float4 cd = scd[dy*SW + dx];

            const bool a0 = (dy-0 >= -RAD) && (dy-0 <= RAD);   // compile-time
            const bool a1 = (dy-1 >= -RAD) && (dy-1 <= RAD);
            const bool a2 = (dy-2 >= -RAD) && (dy-2 <= RAD);
            const bool a3 = (dy-3 >= -RAD) && (dy-3 <= RAD);

            // Broadcast packs shared by both pairs' dots.
            const u64 ax2 = pack2_(nz.x, nz.x);
            const u64 ay2 = pack2_(nz.y, nz.y);
            const u64 az2 = pack2_(nz.z, nz.z);

            if (a0 | a1) {
                const u64 dot2 = fma2_(ax2, NXa, fma2_(ay2, NYa, mul2_(az2, NZa)));
                float d0, d1; unpack2_(d0, d1, dot2);
                const float w0 = wpix_(a0, d0, nz.w, Zc[0], ivd[0],
                                       (dy-0)*(dy-0) + dx*dx);
                const float w1 = wpix_(a1, d1, nz.w, Zc[1], ivd[1],
                                       (dy-1)*(dy-1) + dx*dx);
                const u64 w01 = pack2_(w0, w1);
                arA = fma2_(pack2_(cd.x, cd.x), w01, arA);
                agA = fma2_(pack2_(cd.y, cd.y), w01, agA);
                abA = fma2_(pack2_(cd.z, cd.z), w01, abA);
                awA = add2_(awA, w01);
            }
            if (a2 | a3) {
                const u64 dot2 = fma2_(ax2, NXb, fma2_(ay2, NYb, mul2_(az2, NZb)));
                float d2, d3; unpack2_(d2, d3, dot2);
                const float w2 = wpix_(a2, d2, nz.w, Zc[2], ivd[2],
                                       (dy-2)*(dy-2) + dx*dx);
                const float w3 = wpix_(a3, d3, nz.w, Zc[3], ivd[3],
                                       (dy-3)*(dy-3) + dx*dx);
                const u64 w23 = pack2_(w2, w3);
                arB = fma2_(pack2_(cd.x, cd.x), w23, arB);
                agB = fma2_(pack2_(cd.y, cd.y), w23, agB);
                abB = fma2_(pack2_(cd.z, cd.z), w23, abB);
                awB = add2_(awB, w23);
            }
        }
    }

    float ar[PXY], ag[PXY], ab[PXY], aw[PXY];
    unpack2_(ar[0], ar[1], arA); unpack2_(ar[2], ar[3], arB);
    unpack2_(ag[0], ag[1], agA); unpack2_(ag[2], ag[3], agB);
    unpack2_(ab[0], ab[1], abA); unpack2_(ab[2], ab[3], abB);
    unpack2_(aw[0], aw[1], awA); unpack2_(aw[2], aw[3], awB);

    const int gx  = bx + threadIdx.x;
    const int gy0 = by + threadIdx.y * PXY;
    #pragma unroll
    for (int p = 0; p < PXY; ++p) {
        const int gy = gy0 + p;
        if (gy < IMH) {                              // partial last y-block
            const float inv = 1.0f / fmaxf(aw[p], EPSF);
            float* o = out + ((size_t)gy * IMW + gx) * 3;
            o[0] = ar[p] * inv; o[1] = ag[p] * inv; o[2] = ab[p] * inv;
        }
    }
}

extern "C" void kernel_launch(void* const* d_in, const int* in_sizes, int n_in,
                              void* d_out, int out_size)
{
    const float* in = (const float*)d_in[0];
    float* out = (float*)d_out;
    dim3 block(TBX, TBY);
    dim3 grid(IMW / TBX, (IMH + TILEY - 1) / TILEY);   // 60 x 68
    BilateralDenoiser_44427141710593_kernel<<<grid, block>>>(in, out);
}

// round 12
// speedup vs baseline: 1.2284x; 1.2284x over previous
#include <cuda_runtime.h>

namespace {

constexpr int RAD   = 7;          // N = 2*ceil(2.5)+1 = 7
constexpr int TBX   = 32;         // threads x
constexpr int TBY   = 6;          // threads y
constexpr int PXY   = 2;          // pixels per thread in y
constexpr int TILEY = TBY * PXY;  // 12 output rows per block (1080/12 = 90)
constexpr int SW    = TBX + 2*RAD;    // 46
constexpr int SH    = TILEY + 2*RAD;  // 26
constexpr int IMH   = 1080;
constexpr int IMW   = 1920;
constexpr int CH    = 11;

#define EPSF  1e-4f
#define FCAP  14426.950408889634f          /* 1e4 * log2e */
#define NC2   -0.72134752044448f           /* -0.5*log2e  */

// NINVD_L2E[k] = -log2(e)/sqrt(k); k=0 sentinel -1e30: invdz*(-1e30) -> -huge
// -> fmax(., -FCAP) = -FCAP, matching reference den = max(dz*0, eps) = eps
// (zd = 0 at dsi = 0 anyway).
__device__ constexpr float NINVD_L2E[99] = {
    -1e30f,       -1.44269504f, -1.02014424f, -0.83293944f, -0.72134752f,
    -0.64519935f, -0.58898486f, -0.54529656f, -0.51007212f, -0.48089835f,
    -0.45621984f, -0.43498237f, -0.41646972f, -0.40012747f, -0.38556183f,
    -0.37247373f, -0.36067376f, -0.34990480f, -0.34009409f, -0.33102480f,
    -0.32259967f, -0.31482513f, -0.30758643f, -0.30082509f, -0.29449243f,
    -0.28853901f, -0.28293539f, -0.27764648f, -0.27264828f, -0.26790684f,
    -0.26340594f, -0.25912240f, -0.25503606f, -0.25114328f, -0.24742265f,
    -0.24386200f, -0.24044918f, -0.23717857f, -0.23403768f, -0.23101807f,
    -0.22810992f, -0.22531137f, -0.22261272f, -0.22000923f, -0.21749119f,
    -0.21506125f, -0.21271045f, -0.21043517f, -0.20823486f, -0.20609929f,
    -0.20403378f, -0.20202950f, -0.20008659f, -0.19819969f, -0.19636738f,
    -0.19458680f, -0.19284900f, -0.19115746f, -0.18950668f, -0.18789521f,
    -0.18633688f, -0.18480333f, -0.18331146f, -0.18184540f, -0.18041844f,
    -0.17902041f, -0.17766033f, -0.17632993f, -0.17501816f, -0.17374384f,
    -0.17248900f, -0.17126993f, -0.17004704f, -0.16888040f, -0.16773528f,
    -0.16659174f, -0.16549221f, -0.16440389f, -0.16334410f, -0.16231653f,
    -0.16129984f, -0.16029945f, -0.15932285f, -0.15835942f, -0.15741374f,
    -0.15648424f, -0.15557203f, -0.15467385f, -0.15379850f, -0.15293093f,
    -0.15207893f, -0.15123993f, -0.15041596f, -0.14960526f, -0.14880778f,
    -0.14801817f, -0.14724766f, -0.14648368f, -0.14574043f
};

__device__ __forceinline__ float ex2f_(float x) {
    float y; asm("ex2.approx.f32 %0, %1;" : "=f"(y) : "f"(x)); return y;
}
__device__ __forceinline__ float lg2f_(float x) {
    float y; asm("lg2.approx.f32 %0, %1;" : "=f"(y) : "f"(x)); return y;
}
__device__ __forceinline__ float rcpf_(float x) {
    float y; asm("rcp.approx.f32 %0, %1;" : "=f"(y) : "f"(x)); return y;
}

// ---- packed f32x2 helpers (sm_103a) ----
typedef unsigned long long u64;
__device__ __forceinline__ u64 pack2_(float lo, float hi) {
    u64 d; asm("mov.b64 %0, {%1, %2};" : "=l"(d) : "f"(lo), "f"(hi)); return d;
}
__device__ __forceinline__ void unpack2_(float& lo, float& hi, u64 v) {
    asm("mov.b64 {%0, %1}, %2;" : "=f"(lo), "=f"(hi) : "l"(v));
}
__device__ __forceinline__ u64 mul2_(u64 a, u64 b) {
    u64 d; asm("mul.rn.f32x2 %0, %1, %2;" : "=l"(d) : "l"(a), "l"(b)); return d;
}
__device__ __forceinline__ u64 fma2_(u64 a, u64 b, u64 c) {
    u64 d; asm("fma.rn.f32x2 %0, %1, %2, %3;" : "=l"(d) : "l"(a), "l"(b), "l"(c));
    return d;
}
__device__ __forceinline__ u64 add2_(u64 a, u64 b) {
    u64 d; asm("add.rn.f32x2 %0, %1, %2;" : "=l"(d) : "l"(a), "l"(b)); return d;
}

// Scalar weight, dot already clamped to [0,1]. dsi is compile-time.
// w = ex2( 128*lg2(t) + |zd| * max(invdz*(-c), -FCAP) + NC2*dsi )
// t = 0 -> lg2 = -inf -> w = 0 (matches reference eps^128 fp32 underflow).
__device__ __forceinline__ float wpix_(float t, float ztap,
                                       float Zc, float invdz, int dsi)
{
    float lt  = lg2f_(t);
    float nfp = fmaxf(invdz * NINVD_L2E[dsi], -FCAP);   // <= 0, FMNMX on alu
    float zd  = ztap - Zc;
    return ex2f_(fmaf(lt, 128.0f, fmaf(fabsf(zd), nfp, NC2 * (float)dsi)));
}

} // namespace

__global__ void __launch_bounds__(TBX*TBY, 5)
BilateralDenoiser_44427141710593_kernel(const float* __restrict__ in,
                                        float* __restrict__ out)
{
    __shared__ float4 s_nz[SH * SW];   // (nrm.x, nrm.y, nrm.z, z)
    __shared__ float4 s_cd[SH * SW];   // (col.r, col.g, col.b, dz)

    const int bx  = blockIdx.x * TBX;
    const int by  = blockIdx.y * TILEY;
    const int tid = threadIdx.y * TBX + threadIdx.x;

    // Cooperative halo load; OOB -> zeros => dot=0 -> w=0 (matches reference).
    #pragma unroll
    for (int i = tid; i < SH * SW; i += TBX * TBY) {
        const int ly = i / SW;
        const int lx = i - ly * SW;
        const int gy = by + ly - RAD;
        const int gx = bx + lx - RAD;
        float4 nz = make_float4(0.f, 0.f, 0.f, 0.f);
        float4 cd = make_float4(0.f, 0.f, 0.f, 0.f);
        if ((unsigned)gy < (unsigned)IMH && (unsigned)gx < (unsigned)IMW) {
            const float* p = in + ((size_t)gy * IMW + gx) * CH;
            cd.x = p[0]; cd.y = p[1]; cd.z = p[2];      // col
            nz.x = p[3]; nz.y = p[4]; nz.z = p[5];      // nrm
            nz.w = p[9];                                 // z
            cd.w = p[10];                                // dz
        }
        s_nz[i] = nz;
        s_cd[i] = cd;
    }
    __syncthreads();

    const int c0 = (threadIdx.y * PXY + RAD) * SW + (threadIdx.x + RAD);
    const float4* __restrict__ snz = s_nz + c0;
    const float4* __restrict__ scd = s_cd + c0;

    // Per-pixel center constants (pixels 0 and 1).
    const float4 n0 = snz[0];
    const float4 n1 = snz[SW];
    const float  Zc0 = n0.w, Zc1 = n1.w;
    const float  ivd0 = rcpf_(fmaxf(scd[0].w,  0.0f));
    const float  ivd1 = rcpf_(fmaxf(scd[SW].w, 0.0f));

    // Hoisted packed normals: lane0 = pixel0, lane1 = pixel1.
    const u64 NX2 = pack2_(n0.x, n1.x);
    const u64 NY2 = pack2_(n0.y, n1.y);
    const u64 NZ2 = pack2_(n0.z, n1.z);

    // Packed accumulators: lane0 = pixel0, lane1 = pixel1.
    u64 ar2 = 0ull, ag2 = 0ull, ab2 = 0ull, aw2 = 0ull;

    // One smem load per (dy,dx) feeds pixel0's tap (dy) and pixel1's (dy-1).
    #pragma unroll
    for (int dy = -RAD; dy <= RAD + 1; ++dy) {
        #pragma unroll
        for (int dx = -RAD; dx <= RAD; ++dx) {
            const float4 nz = snz[dy*SW + dx];
            const float4 cd = scd[dy*SW + dx];

            // Packed dot for both pixels (one broadcast set, 3 f32x2 ops).
            const u64 ax2 = pack2_(nz.x, nz.x);
            const u64 ay2 = pack2_(nz.y, nz.y);
            const u64 az2 = pack2_(nz.z, nz.z);
            const u64 dot2 = fma2_(ax2, NX2, fma2_(ay2, NY2, mul2_(az2, NZ2)));
            float d0, d1; unpack2_(d0, d1, dot2);

            // Clamp on the ALU pipe (FMNMX x2 per pixel).
            float w0 = 0.0f, w1 = 0.0f;
            if (dy <= RAD) {                            // compile-time
                const float t0 = fminf(fmaxf(d0, 0.0f), 1.0f);
                w0 = wpix_(t0, nz.w, Zc0, ivd0, dy*dy + dx*dx);
            }
            if (dy >= -RAD + 1) {                       // compile-time
                const float t1 = fminf(fmaxf(d1, 0.0f), 1.0f);
                w1 = wpix_(t1, nz.w, Zc1, ivd1, (dy-1)*(dy-1) + dx*dx);
            }

            // Packed accumulation (both pixels).
            const u64 w01 = pack2_(w0, w1);
            ar2 = fma2_(pack2_(cd.x, cd.x), w01, ar2);
            ag2 = fma2_(pack2_(cd.y, cd.y), w01, ag2);
            ab2 = fma2_(pack2_(cd.z, cd.z), w01, ab2);
            aw2 = add2_(aw2, w01);
        }
    }

    float ar0, ar1, ag0, ag1, ab0, ab1, aw0, aw1;
    unpack2_(ar0, ar1, ar2);
    unpack2_(ag0, ag1, ag2);
    unpack2_(ab0, ab1, ab2);
    unpack2_(aw0, aw1, aw2);

    const int gx  = bx + threadIdx.x;
    const int gy0 = by + threadIdx.y * PXY;
    {
        const float inv = 1.0f / fmaxf(aw0, EPSF);
        float* o = out + ((size_t)gy0 * IMW + gx) * 3;
        o[0] = ar0 * inv; o[1] = ag0 * inv; o[2] = ab0 * inv;
    }
    {
        const float inv = 1.0f / fmaxf(aw1, EPSF);
        float* o = out + ((size_t)(gy0 + 1) * IMW + gx) * 3;
        o[0] = ar1 * inv; o[1] = ag1 * inv; o[2] = ab1 * inv;
    }
}

extern "C" void kernel_launch(void* const* d_in, const int* in_sizes, int n_in,
                              void* d_out, int out_size)
{
    const float* in = (const float*)d_in[0];
    float* out = (float*)d_out;
    dim3 block(TBX, TBY);
    dim3 grid(IMW / TBX, IMH / TILEY);   // 60 x 90, exact tiling
    BilateralDenoiser_44427141710593_kernel<<<grid, block>>>(in, out);
}